// round 11
// baseline (speedup 1.0000x reference)
#include <cuda_runtime.h>
#include <cuda_bf16.h>
#include <math.h>
#include <stdint.h>

#define BB   16
#define CIN  64
#define CO   64
#define HIDD 16
#define TT   16
#define HW   1024

// ---------------------------------------------------------------------------
// Persistent device scratch (allocation-free)
// ---------------------------------------------------------------------------
__device__ float g_c [BB*HW*CO];            // cell state, layout [b][pix][c]
__device__ float g_conv[BB*HW*256];         // conv out, layout [b][pix][oc256]
__device__ __nv_bfloat16 g_wp[18*2*16384];  // conv weights hi/lo
__device__ float g_peep[3*HW*CO];           // peepholes transposed [w][pix][c]
// pre-split bf16 conv inputs, rows of 64 bf16 = 8 uint4
__device__ uint4 g_xhi[BB*TT*HW*8];         // X hi, [b][t][pix][ci]
__device__ uint4 g_xlo[BB*TT*HW*8];
__device__ uint4 g_hhi[BB*HW*8];            // h hi, [b][pix][ci]
__device__ uint4 g_hlo[BB*HW*8];
// packed attention operands (bf16 hi/lo)
__device__ uint4 g_qh[BB*HW*2];             // q [b][n][j16]
__device__ uint4 g_ql[BB*HW*2];
__device__ uint4 g_kh[BB*HW*2];             // k [b][m][j16]
__device__ uint4 g_kl[BB*HW*2];
__device__ uint32_t g_vh32[BB*CO*512];      // v [b][c][m-pairs]
__device__ uint32_t g_vl32[BB*CO*512];
__device__ uint32_t g_zwh32[2048];          // zw [co][c]
__device__ uint32_t g_zwl32[2048];

__device__ __forceinline__ uint32_t smem_u32(const void* p) {
    uint32_t a;
    asm("{ .reg .u64 t; cvta.to.shared.u64 t, %1; cvt.u32.u64 %0, t; }"
        : "=r"(a) : "l"(p));
    return a;
}
__device__ __forceinline__ uint32_t pack_bf16x2(float lo, float hi) {
    uint32_t r;
    asm("cvt.rn.bf16x2.f32 %0, %1, %2;" : "=r"(r) : "f"(hi), "f"(lo));
    return r;
}
__device__ __forceinline__ void ldsm_x4(uint32_t addr, uint32_t r[4]) {
    asm volatile("ldmatrix.sync.aligned.m8n8.x4.shared.b16 {%0,%1,%2,%3}, [%4];"
        : "=r"(r[0]), "=r"(r[1]), "=r"(r[2]), "=r"(r[3]) : "r"(addr));
}
__device__ __forceinline__ void mma_bf16(float d[4], const uint32_t a[4],
                                         uint32_t b0, uint32_t b1) {
    asm volatile("mma.sync.aligned.m16n8k16.row.col.f32.bf16.bf16.f32 "
        "{%0,%1,%2,%3}, {%4,%5,%6,%7}, {%8,%9}, {%0,%1,%2,%3};"
        : "+f"(d[0]), "+f"(d[1]), "+f"(d[2]), "+f"(d[3])
        : "r"(a[0]), "r"(a[1]), "r"(a[2]), "r"(a[3]), "r"(b0), "r"(b1));
}
// exp on FMA pipe: exp(x) = 2^(x*log2e), degree-6 poly, exponent bit-add
__device__ __forceinline__ float fexp(float x) {
    float y = x * 1.4426950408889634f;
    int k = __float2int_rn(y);
    float f = y - (float)k;
    float p = 1.5403530393381610e-4f;
    p = p * f + 1.3333558146428443e-3f;
    p = p * f + 9.6181291076284772e-3f;
    p = p * f + 5.5504108664821580e-2f;
    p = p * f + 2.4022650695910071e-1f;
    p = p * f + 6.9314718055994531e-1f;
    p = p * f + 1.0f;
    return __int_as_float(__float_as_int(p) + (k << 23));
}
__device__ __forceinline__ uint32_t resid_pack(uint32_t hp, float a, float b) {
    float ha = __uint_as_float(hp << 16);
    float hb = __uint_as_float(hp & 0xFFFF0000u);
    return pack_bf16x2(a - ha, b - hb);
}

__global__ void zero_state() {
    int i = blockIdx.x * blockDim.x + threadIdx.x;
    if (i < BB*HW*CO) g_c[i] = 0.f;
    if (i < BB*HW*8) {
        uint4 z = make_uint4(0, 0, 0, 0);
        g_hhi[i] = z; g_hlo[i] = z;
    }
}

__device__ __forceinline__ float sigm(float x) { return 1.f / (1.f + __expf(-x)); }

// ---------------------------------------------------------------------------
// One-time preps
// ---------------------------------------------------------------------------
__global__ void prep_weights(const float* __restrict__ conv_w) {
    int idx = blockIdx.x * blockDim.x + threadIdx.x;
    if (idx >= 18*16384) return;
    int k     = idx & 63;
    int oc    = (idx >> 6) & 255;
    int chunk = idx >> 14;
    int tap = chunk >> 1, half = chunk & 1;
    int ci  = half * 64 + k;
    float w = conv_w[(oc*128 + ci)*9 + tap];
    __nv_bfloat16 hi = __float2bfloat16_rn(w);
    __nv_bfloat16 lo = __float2bfloat16_rn(w - __bfloat162float(hi));
    g_wp[(size_t)(chunk*2 + 0)*16384 + oc*64 + k] = hi;
    g_wp[(size_t)(chunk*2 + 1)*16384 + oc*64 + k] = lo;
}

__global__ void prep_peep(const float* __restrict__ Wci,
                          const float* __restrict__ Wcf,
                          const float* __restrict__ Wco) {
    int idx = blockIdx.x * blockDim.x + threadIdx.x;
    if (idx >= 3*CO*HW) return;
    int w = idx >> 16;
    int rem = idx & 65535;
    int c = rem >> 10, pix = rem & 1023;
    const float* src = (w == 0) ? Wci : (w == 1) ? Wcf : Wco;
    g_peep[((size_t)w*HW + pix)*CO + c] = src[c*HW + pix];
}

__global__ void prep_zw(const float* __restrict__ zw) {
    int idx = blockIdx.x * blockDim.x + threadIdx.x;
    if (idx >= 2048) return;
    int co = idx >> 5, cp = idx & 31;
    float a = zw[co*64 + 2*cp], b = zw[co*64 + 2*cp + 1];
    uint32_t hp = pack_bf16x2(a, b);
    g_zwh32[idx] = hp;
    g_zwl32[idx] = resid_pack(hp, a, b);
}

// X transpose + hi/lo split: [b][ci][t][pix] f32 -> [b][t][pix][ci] bf16 x2
__global__ __launch_bounds__(256) void prep_x(const float* __restrict__ X) {
    __shared__ float tile[64][133];
    const int tid = threadIdx.x;
    const int p0 = blockIdx.x * 128;
    const int t = blockIdx.y, b = blockIdx.z;
    for (int i = tid; i < 64*128; i += 256) {
        int ci = i >> 7, p = i & 127;
        tile[ci][p] = X[((size_t)(b*64 + ci)*16 + t)*1024 + p0 + p];
    }
    __syncthreads();
    for (int i = tid; i < 1024; i += 256) {
        int p = i >> 3, q = i & 7;
        uint32_t hi[4], lo[4];
#pragma unroll
        for (int j = 0; j < 4; j++) {
            float a = tile[q*8 + 2*j][p], bv = tile[q*8 + 2*j + 1][p];
            uint32_t hp = pack_bf16x2(a, bv);
            hi[j] = hp;
            lo[j] = resid_pack(hp, a, bv);
        }
        size_t o = ((size_t)(b*TT + t)*HW + p0 + p)*8 + q;
        g_xhi[o] = make_uint4(hi[0], hi[1], hi[2], hi[3]);
        g_xlo[o] = make_uint4(lo[0], lo[1], lo[2], lo[3]);
    }
}

// ---------------------------------------------------------------------------
// Conv as implicit GEMM on mma.sync bf16 (hi/lo 3-term split).
// ---------------------------------------------------------------------------
#define PR 144
#define OFF_A_HI 0
#define OFF_A_LO 29376
#define OFF_B_HI 58752
#define OFF_B_LO 77184
#define CONV_SMEM 95616

__global__ __launch_bounds__(256) void conv_mma_kernel(int t)
{
    extern __shared__ char sm[];
    const uint32_t sb = smem_u32(sm);
    const int tid = threadIdx.x;
    const int lane = tid & 31, warp = tid >> 5;
    const int tile = blockIdx.x, b = blockIdx.y, nhalf = blockIdx.z;
    const int r0 = tile * 4;
    const int warpM = (warp & 3) * 32;
    const int warpN = (warp >> 2) * 64;

    float acc[2][8][4];
#pragma unroll
    for (int mt = 0; mt < 2; mt++)
#pragma unroll
        for (int nt = 0; nt < 8; nt++)
#pragma unroll
            for (int i = 0; i < 4; i++) acc[mt][nt][i] = 0.f;

    int aofs[2];
    {
        int m_off = (lane & 7) + ((lane >> 3) & 1) * 8;
        int kb = (lane >> 4) * 16;
#pragma unroll
        for (int mt = 0; mt < 2; mt++) {
            int m = warpM + mt*16 + m_off;
            int hp = ((m >> 5) + 1)*34 + (m & 31) + 1;
            aofs[mt] = hp*PR + kb;
        }
    }
    const uint32_t boff = ((lane & 7) + (lane >> 4) * 8) * PR
                        + ((lane >> 3) & 1) * 16 + warpN*PR;

    for (int half = 0; half < 2; half++) {
        {
            const uint4* shi; const uint4* slo;
            if (half == 0) {
                shi = g_xhi + (size_t)(b*TT + t)*HW*8;
                slo = g_xlo + (size_t)(b*TT + t)*HW*8;
            } else {
                shi = g_hhi + (size_t)b*HW*8;
                slo = g_hlo + (size_t)b*HW*8;
            }
#pragma unroll 2
            for (int i = tid; i < 1632; i += 256) {
                int pix = i >> 3, q = i & 7;
                int hr = pix / 34, hc = pix - hr*34;
                int gr = r0 + hr - 1, gc = hc - 1;
                uint4 vhi = make_uint4(0,0,0,0), vlo = vhi;
                if (gr >= 0 && gr < 32 && gc >= 0 && gc < 32) {
                    int gp = gr*32 + gc;
                    vhi = shi[gp*8 + q];
                    vlo = slo[gp*8 + q];
                }
                *(uint4*)(sm + OFF_A_HI + pix*PR + q*16) = vhi;
                *(uint4*)(sm + OFF_A_LO + pix*PR + q*16) = vlo;
            }
        }

        for (int tap = 0; tap < 9; tap++) {
            const int dr = tap/3 - 1, dc = tap%3 - 1;
            const int tapd = (dr*34 + dc)*PR;
            {
                const uint4* wsrc = (const uint4*)g_wp
                    + (size_t)(tap*2 + half)*4096 + nhalf*1024;
#pragma unroll 2
                for (int i = tid; i < 2048; i += 256) {
                    int term = i >> 10, r = (i >> 3) & 127, q = i & 7;
                    uint4 v = wsrc[term*2048 + r*8 + q];
                    *(uint4*)(sm + (term ? OFF_B_LO : OFF_B_HI) + r*PR + q*16) = v;
                }
            }
            __syncthreads();

#pragma unroll
            for (int ks = 0; ks < 4; ks++) {
                uint32_t ah[2][4], al[2][4];
#pragma unroll
                for (int mt = 0; mt < 2; mt++) {
                    ldsm_x4(sb + OFF_A_HI + aofs[mt] + tapd + ks*32, ah[mt]);
                    ldsm_x4(sb + OFF_A_LO + aofs[mt] + tapd + ks*32, al[mt]);
                }
#pragma unroll
                for (int ng = 0; ng < 4; ng++) {
                    uint32_t bh[4], bl[4];
                    ldsm_x4(sb + OFF_B_HI + boff + ng*(16*PR) + ks*32, bh);
                    ldsm_x4(sb + OFF_B_LO + boff + ng*(16*PR) + ks*32, bl);
#pragma unroll
                    for (int mt = 0; mt < 2; mt++) {
                        mma_bf16(acc[mt][2*ng],   ah[mt], bh[0], bh[1]);
                        mma_bf16(acc[mt][2*ng+1], ah[mt], bh[2], bh[3]);
                        mma_bf16(acc[mt][2*ng],   al[mt], bh[0], bh[1]);
                        mma_bf16(acc[mt][2*ng+1], al[mt], bh[2], bh[3]);
                        mma_bf16(acc[mt][2*ng],   ah[mt], bl[0], bl[1]);
                        mma_bf16(acc[mt][2*ng+1], ah[mt], bl[2], bl[3]);
                    }
                }
            }
            __syncthreads();
        }
    }

    {
        const int rbase = tile*128 + warpM + (lane >> 2);
        const int cbase = nhalf*128 + warpN + 2*(lane & 3);
        float* gout = g_conv + (size_t)b*HW*256;
#pragma unroll
        for (int mt = 0; mt < 2; mt++) {
#pragma unroll
            for (int nt = 0; nt < 8; nt++) {
                int pix = rbase + mt*16;
                int oc  = cbase + nt*8;
                *(float2*)(gout + (size_t)pix*256 + oc) =
                    make_float2(acc[mt][nt][0], acc[mt][nt][1]);
                *(float2*)(gout + (size_t)(pix + 8)*256 + oc) =
                    make_float2(acc[mt][nt][2], acc[mt][nt][3]);
            }
        }
    }
}

// ---------------------------------------------------------------------------
// Fused gates + qkv GEMM + bf16 hi/lo pack. Grid (8 pixel-tiles, B), 256 thr.
// Stage 1: gates from g_conv -> g_c + h_n in smem [64 c][132 pad].
// Stage 2: 96x64 GEMM; lane owns 4 consecutive pixels (float4 LDS).
// Epilogue: pack q/k (j-pairs, in-thread row pairs) and v (m-pairs) directly.
// ---------------------------------------------------------------------------
#define GQKV_SMEM ((64*132 + 96*64 + 96) * 4)

__global__ __launch_bounds__(256) void gqkv_kernel(
    const float* __restrict__ conv_b,
    const float* __restrict__ qw, const float* __restrict__ qb,
    const float* __restrict__ kw, const float* __restrict__ kb,
    const float* __restrict__ vw, const float* __restrict__ vb)
{
    extern __shared__ float smf[];
    float* s_h = smf;                    // [64][132]
    float* s_w = smf + 64*132;           // [96][64]
    float* s_b = smf + 64*132 + 96*64;   // [96]

    const int tid = threadIdx.x;
    const int b  = blockIdx.y;
    const int p0 = blockIdx.x * 128;

    // stage projection weights + biases
    for (int idx = tid; idx < 96*64; idx += 256) {
        int r = idx >> 6, c = idx & 63;
        float v;
        if (r < 16)      v = qw[r*64 + c];
        else if (r < 32) v = kw[(r - 16)*64 + c];
        else             v = vw[(r - 32)*64 + c];
        s_w[idx] = v;
    }
    if (tid < 96) s_b[tid] = (tid < 16) ? qb[tid]
                            : (tid < 32) ? kb[tid - 16] : vb[tid - 32];

    // stage 1: LSTM gates -> g_c (gmem) + h_n (smem)
    for (int i = tid; i < 8192; i += 256) {
        int c = i & 63, p = i >> 6;
        int pix = p0 + p;
        size_t row = ((size_t)b*HW + pix)*256;
        float ic = g_conv[row + c];
        float fc = g_conv[row + 64 + c];
        float gc = g_conv[row + 128 + c];
        float oc = g_conv[row + 192 + c];
        size_t ci = ((size_t)b*HW + pix)*CO + c;
        float cold = g_c[ci];
        size_t pp = (size_t)pix*CO + c;
        float iG = sigm(ic + conv_b[c]       + g_peep[pp] * cold);
        float fG = sigm(fc + conv_b[64 + c]  + g_peep[(size_t)HW*CO + pp] * cold);
        float nc = fG * cold + iG * tanhf(gc + conv_b[128 + c]);
        float oG = sigm(oc + conv_b[192 + c] + g_peep[(size_t)2*HW*CO + pp] * nc);
        g_c[ci] = nc;
        s_h[c*132 + p] = oG * tanhf(nc);
    }
    __syncthreads();

    // stage 2: GEMM, lane -> 4 consecutive pixels
    const int lane = tid & 31, grp = tid >> 5;
    float acc[12][4];
#pragma unroll
    for (int rl = 0; rl < 12; rl++)
#pragma unroll
        for (int p = 0; p < 4; p++) acc[rl][p] = 0.f;

    for (int c = 0; c < 64; c++) {
        float4 hv = *(const float4*)(s_h + c*132 + lane*4);
#pragma unroll
        for (int rl = 0; rl < 12; rl++) {
            float wv = s_w[(grp*12 + rl)*64 + c];
            acc[rl][0] += wv * hv.x;
            acc[rl][1] += wv * hv.y;
            acc[rl][2] += wv * hv.z;
            acc[rl][3] += wv * hv.w;
        }
    }

    // epilogue: add bias, pack bf16 hi/lo, store
    const int n0 = p0 + lane*4;
#pragma unroll
    for (int rl = 0; rl < 12; rl++) {
        float bia = s_b[grp*12 + rl];
#pragma unroll
        for (int p = 0; p < 4; p++) acc[rl][p] += bia;
    }
#pragma unroll
    for (int rl = 0; rl < 12; rl++) {
        int r = grp*12 + rl;
        if (r < 32) {
            if ((r & 1) == 0) {
                // q/k: pack channel pair (r, r+1) per pixel
                uint32_t* dh = (uint32_t*)((r < 16) ? g_qh : g_kh);
                uint32_t* dl = (uint32_t*)((r < 16) ? g_ql : g_kl);
                int jp = (r & 15) >> 1;
#pragma unroll
                for (int p = 0; p < 4; p++) {
                    float a = acc[rl][p], c2 = acc[rl + 1][p];
                    uint32_t hp = pack_bf16x2(a, c2);
                    size_t o = ((size_t)b*HW + n0 + p)*8 + jp;
                    dh[o] = hp;
                    dl[o] = resid_pack(hp, a, c2);
                }
            }
        } else {
            // v: pack pixel pairs (m-pairs)
            int c = r - 32;
            size_t o = ((size_t)(b*CO + c))*512 + (n0 >> 1);
            uint32_t h0 = pack_bf16x2(acc[rl][0], acc[rl][1]);
            uint32_t h1 = pack_bf16x2(acc[rl][2], acc[rl][3]);
            g_vh32[o]     = h0;
            g_vl32[o]     = resid_pack(h0, acc[rl][0], acc[rl][1]);
            g_vh32[o + 1] = h1;
            g_vl32[o + 1] = resid_pack(h1, acc[rl][2], acc[rl][3]);
        }
    }
}

// ---------------------------------------------------------------------------
// MMA attention + fused z-projection. (unchanged from R9)
// ---------------------------------------------------------------------------
#define AQH 0
#define AQL 6144
#define AKH 12288
#define AKL 18432
#define AVH 24576
#define AVL 41984
#define AZH 59392
#define AZL 68608
#define ATTN2_SMEM 77824

__global__ __launch_bounds__(256) void attn_mma(
    const float* __restrict__ zb, float* __restrict__ out, int tstep)
{
    extern __shared__ char sm[];
    const uint32_t sbase = smem_u32(sm);
    const int tid = threadIdx.x, lane = tid & 31, warp = tid >> 5;
    const int b = blockIdx.y, tile = blockIdx.x;
    const int n0 = tile * 128;

    {
        int row = tid & 127, term = tid >> 7;
        const uint4* src = (term ? g_ql : g_qh) + ((size_t)b*HW + n0 + row)*2;
        char* dst = sm + (term ? AQL : AQH) + row*48;
        ((uint4*)dst)[0] = src[0];
        ((uint4*)dst)[1] = src[1];
    }
    for (int i = tid; i < 1024; i += 256) {
        int term = i >> 9, r = (i >> 3) & 63, q = i & 7;
        const uint4* s32 = (const uint4*)(term ? g_zwl32 : g_zwh32);
        *(uint4*)(sm + (term ? AZL : AZH) + r*144 + q*16) = s32[r*8 + q];
    }
    __syncthreads();

    uint32_t aq_hi[4], aq_lo[4];
    {
        uint32_t aaddr = sbase + AQH
            + (warp*16 + (lane & 7) + ((lane >> 3) & 1)*8)*48 + (lane >> 4)*16;
        ldsm_x4(aaddr, aq_hi);
        ldsm_x4(aaddr + (AQL - AQH), aq_lo);
    }
    const uint32_t kaddr = sbase + AKH + ((lane & 7) + (lane >> 4)*8)*48
                         + ((lane >> 3) & 1)*16;
    const uint32_t vaddr = sbase + AVH + ((lane & 7) + (lane >> 4)*8)*272
                         + ((lane >> 3) & 1)*16;
    const uint32_t zaddr = sbase + AZH + ((lane & 7) + (lane >> 4)*8)*144
                         + ((lane >> 3) & 1)*16;

    float pv[8][4];
#pragma unroll
    for (int i = 0; i < 8; i++)
#pragma unroll
        for (int j = 0; j < 4; j++) pv[i][j] = 0.f;
    float L0 = 0.f, L1 = 0.f;

    for (int mt = 0; mt < 8; mt++) {
        __syncthreads();
        {
            int row = tid & 127, term = tid >> 7;
            const uint4* src = (term ? g_kl : g_kh)
                             + ((size_t)b*HW + mt*128 + row)*2;
            char* dst = sm + (term ? AKL : AKH) + row*48;
            ((uint4*)dst)[0] = src[0];
            ((uint4*)dst)[1] = src[1];
        }
#pragma unroll 2
        for (int i = tid; i < 2048; i += 256) {
            int term = i >> 10, r = (i >> 4) & 63, q = i & 15;
            const uint4* src = (const uint4*)(term ? g_vl32 : g_vh32);
            uint4 v = src[((size_t)(b*CO) + r)*128 + mt*16 + q];
            *(uint4*)(sm + (term ? AVL : AVH) + r*272 + q*16) = v;
        }
        __syncthreads();

        float sacc[16][4];
#pragma unroll
        for (int i = 0; i < 16; i++)
#pragma unroll
            for (int j = 0; j < 4; j++) sacc[i][j] = 0.f;
#pragma unroll
        for (int mg = 0; mg < 8; mg++) {
            uint32_t bh[4], bl[4];
            ldsm_x4(kaddr + mg*(16*48), bh);
            ldsm_x4(kaddr + (AKL - AKH) + mg*(16*48), bl);
            mma_bf16(sacc[2*mg],   aq_hi, bh[0], bh[1]);
            mma_bf16(sacc[2*mg+1], aq_hi, bh[2], bh[3]);
            mma_bf16(sacc[2*mg],   aq_lo, bh[0], bh[1]);
            mma_bf16(sacc[2*mg+1], aq_lo, bh[2], bh[3]);
            mma_bf16(sacc[2*mg],   aq_hi, bl[0], bl[1]);
            mma_bf16(sacc[2*mg+1], aq_hi, bl[2], bl[3]);
        }

#pragma unroll
        for (int j = 0; j < 8; j++) {
            float e0 = fexp(sacc[2*j][0]),   e1 = fexp(sacc[2*j][1]);
            float e2 = fexp(sacc[2*j][2]),   e3 = fexp(sacc[2*j][3]);
            float e4 = fexp(sacc[2*j+1][0]), e5 = fexp(sacc[2*j+1][1]);
            float e6 = fexp(sacc[2*j+1][2]), e7 = fexp(sacc[2*j+1][3]);
            L0 += e0 + e1 + e4 + e5;
            L1 += e2 + e3 + e6 + e7;
            uint32_t ah[4], al[4];
            ah[0] = pack_bf16x2(e0, e1); al[0] = resid_pack(ah[0], e0, e1);
            ah[1] = pack_bf16x2(e2, e3); al[1] = resid_pack(ah[1], e2, e3);
            ah[2] = pack_bf16x2(e4, e5); al[2] = resid_pack(ah[2], e4, e5);
            ah[3] = pack_bf16x2(e6, e7); al[3] = resid_pack(ah[3], e6, e7);
#pragma unroll
            for (int cg = 0; cg < 4; cg++) {
                uint32_t vh[4], vl[4];
                ldsm_x4(vaddr + cg*(16*272) + j*32, vh);
                ldsm_x4(vaddr + (AVL - AVH) + cg*(16*272) + j*32, vl);
                mma_bf16(pv[2*cg],   ah, vh[0], vh[1]);
                mma_bf16(pv[2*cg+1], ah, vh[2], vh[3]);
                mma_bf16(pv[2*cg],   al, vh[0], vh[1]);
                mma_bf16(pv[2*cg+1], al, vh[2], vh[3]);
                mma_bf16(pv[2*cg],   ah, vl[0], vl[1]);
                mma_bf16(pv[2*cg+1], ah, vl[2], vl[3]);
            }
        }
    }

    L0 += __shfl_xor_sync(0xFFFFFFFFu, L0, 1);
    L0 += __shfl_xor_sync(0xFFFFFFFFu, L0, 2);
    L1 += __shfl_xor_sync(0xFFFFFFFFu, L1, 1);
    L1 += __shfl_xor_sync(0xFFFFFFFFu, L1, 2);
    float inv0 = 1.f / L0, inv1 = 1.f / L1;

    float zp[8][4];
#pragma unroll
    for (int i = 0; i < 8; i++)
#pragma unroll
        for (int j = 0; j < 4; j++) zp[i][j] = 0.f;
#pragma unroll
    for (int ck = 0; ck < 4; ck++) {
        uint32_t ah[4], al[4];
        ah[0] = pack_bf16x2(pv[2*ck][0], pv[2*ck][1]);
        al[0] = resid_pack(ah[0], pv[2*ck][0], pv[2*ck][1]);
        ah[1] = pack_bf16x2(pv[2*ck][2], pv[2*ck][3]);
        al[1] = resid_pack(ah[1], pv[2*ck][2], pv[2*ck][3]);
        ah[2] = pack_bf16x2(pv[2*ck+1][0], pv[2*ck+1][1]);
        al[2] = resid_pack(ah[2], pv[2*ck+1][0], pv[2*ck+1][1]);
        ah[3] = pack_bf16x2(pv[2*ck+1][2], pv[2*ck+1][3]);
        al[3] = resid_pack(ah[3], pv[2*ck+1][2], pv[2*ck+1][3]);
#pragma unroll
        for (int cog = 0; cog < 4; cog++) {
            uint32_t bh[4], bl[4];
            ldsm_x4(zaddr + cog*(16*144) + ck*32, bh);
            ldsm_x4(zaddr + (AZL - AZH) + cog*(16*144) + ck*32, bl);
            mma_bf16(zp[2*cog],   ah, bh[0], bh[1]);
            mma_bf16(zp[2*cog+1], ah, bh[2], bh[3]);
            mma_bf16(zp[2*cog],   al, bh[0], bh[1]);
            mma_bf16(zp[2*cog+1], al, bh[2], bh[3]);
            mma_bf16(zp[2*cog],   ah, bl[0], bl[1]);
            mma_bf16(zp[2*cog+1], ah, bl[2], bl[3]);
        }
    }

    {
        const int r0 = warp*16 + (lane >> 2);
        const int pix = n0 + r0;
        uint32_t* hh = (uint32_t*)g_hhi + ((size_t)b*HW + pix)*32;
        uint32_t* hl = (uint32_t*)g_hlo + ((size_t)b*HW + pix)*32;
#pragma unroll
        for (int cog = 0; cog < 4; cog++) {
#pragma unroll
            for (int tt = 0; tt < 2; tt++) {
                int co = cog*16 + tt*8 + 2*(lane & 3);
                float bz0 = __ldg(zb + co), bz1 = __ldg(zb + co + 1);
                float v0 = zp[2*cog+tt][0]*inv0 + bz0;
                float v1 = zp[2*cog+tt][1]*inv0 + bz1;
                float v2 = zp[2*cog+tt][2]*inv1 + bz0;
                float v3 = zp[2*cog+tt][3]*inv1 + bz1;
                size_t o0 = ((size_t)(b*CO + co)*TT + tstep)*HW;
                size_t o1 = ((size_t)(b*CO + co + 1)*TT + tstep)*HW;
                out[o0 + pix]     = v0;
                out[o1 + pix]     = v1;
                out[o0 + pix + 8] = v2;
                out[o1 + pix + 8] = v3;
                int ci = cog*8 + tt*4 + (lane & 3);
                uint32_t hp0 = pack_bf16x2(v0, v1);
                hh[ci] = hp0;
                hl[ci] = resid_pack(hp0, v0, v1);
                uint32_t hp1 = pack_bf16x2(v2, v3);
                hh[256 + ci] = hp1;
                hl[256 + ci] = resid_pack(hp1, v2, v3);
            }
        }
    }
}

// ---------------------------------------------------------------------------
extern "C" void kernel_launch(void* const* d_in, const int* in_sizes, int n_in,
                              void* d_out, int out_size)
{
    (void)in_sizes; (void)n_in; (void)out_size;
    const float* X      = (const float*)d_in[0];
    const float* conv_w = (const float*)d_in[1];
    const float* conv_b = (const float*)d_in[2];
    const float* W_ci   = (const float*)d_in[3];
    const float* W_cf   = (const float*)d_in[4];
    const float* W_co   = (const float*)d_in[5];
    const float* q_w    = (const float*)d_in[6];
    const float* q_b    = (const float*)d_in[7];
    const float* k_w    = (const float*)d_in[8];
    const float* k_b    = (const float*)d_in[9];
    const float* v_w    = (const float*)d_in[10];
    const float* v_b    = (const float*)d_in[11];
    const float* z_w    = (const float*)d_in[12];
    const float* z_b    = (const float*)d_in[13];
    float* out = (float*)d_out;

    cudaFuncSetAttribute(conv_mma_kernel,
        cudaFuncAttributeMaxDynamicSharedMemorySize, CONV_SMEM);
    cudaFuncSetAttribute(gqkv_kernel,
        cudaFuncAttributeMaxDynamicSharedMemorySize, GQKV_SMEM);
    cudaFuncSetAttribute(attn_mma,
        cudaFuncAttributeMaxDynamicSharedMemorySize, ATTN2_SMEM);

    zero_state<<<(BB*HW*CO + 255)/256, 256>>>();
    prep_weights<<<(18*16384 + 255)/256, 256>>>(conv_w);
    prep_peep<<<(3*CO*HW + 255)/256, 256>>>(W_ci, W_cf, W_co);
    prep_zw<<<8, 256>>>(z_w);
    prep_x<<<dim3(8, TT, BB), 256>>>(X);

    for (int t = 0; t < TT; t++) {
        conv_mma_kernel<<<dim3(8, BB, 2), 256, CONV_SMEM>>>(t);
        gqkv_kernel<<<dim3(8, BB), 256, GQKV_SMEM>>>(
            conv_b, q_w, q_b, k_w, k_b, v_w, v_b);
        attn_mma<<<dim3(8, BB), 256, ATTN2_SMEM>>>(z_b, out, t);
    }
}

// round 13
// speedup vs baseline: 1.0995x; 1.0995x over previous
#include <cuda_runtime.h>
#include <cuda_bf16.h>
#include <math.h>
#include <stdint.h>

#define BB   16
#define CIN  64
#define CO   64
#define HIDD 16
#define TT   16
#define HW   1024

// ---------------------------------------------------------------------------
// Persistent device scratch (allocation-free)
// ---------------------------------------------------------------------------
__device__ float g_c [BB*HW*CO];            // cell state, layout [b][pix][c]
__device__ float g_hn[BB*HW*CO];            // new_h,      layout [b][pix][c]
__device__ float g_conv[BB*HW*256];         // conv out, layout [b][pix][oc256]
__device__ __nv_bfloat16 g_wp[18*2*16384];  // conv weights hi/lo
__device__ float g_peep[3*HW*CO];           // peepholes transposed [w][pix][c]
// pre-split bf16 conv inputs, rows of 64 bf16 = 8 uint4
__device__ uint4 g_xhi[BB*TT*HW*8];         // X hi, [b][t][pix][ci]
__device__ uint4 g_xlo[BB*TT*HW*8];
__device__ uint4 g_hhi[BB*HW*8];            // h hi, [b][pix][ci]
__device__ uint4 g_hlo[BB*HW*8];
// packed attention operands (bf16 hi/lo)
__device__ uint4 g_qh[BB*HW*2];             // q [b][n][j16]
__device__ uint4 g_ql[BB*HW*2];
__device__ uint4 g_kh[BB*HW*2];             // k [b][m][j16]
__device__ uint4 g_kl[BB*HW*2];
__device__ uint32_t g_vh32[BB*CO*512];      // v [b][c][m-pairs]
__device__ uint32_t g_vl32[BB*CO*512];
__device__ uint32_t g_zwh32[2048];          // zw [co][c]
__device__ uint32_t g_zwl32[2048];

__device__ __forceinline__ uint32_t smem_u32(const void* p) {
    uint32_t a;
    asm("{ .reg .u64 t; cvta.to.shared.u64 t, %1; cvt.u32.u64 %0, t; }"
        : "=r"(a) : "l"(p));
    return a;
}
__device__ __forceinline__ uint32_t pack_bf16x2(float lo, float hi) {
    uint32_t r;
    asm("cvt.rn.bf16x2.f32 %0, %1, %2;" : "=r"(r) : "f"(hi), "f"(lo));
    return r;
}
__device__ __forceinline__ void ldsm_x4(uint32_t addr, uint32_t r[4]) {
    asm volatile("ldmatrix.sync.aligned.m8n8.x4.shared.b16 {%0,%1,%2,%3}, [%4];"
        : "=r"(r[0]), "=r"(r[1]), "=r"(r[2]), "=r"(r[3]) : "r"(addr));
}
__device__ __forceinline__ void mma_bf16(float d[4], const uint32_t a[4],
                                         uint32_t b0, uint32_t b1) {
    asm volatile("mma.sync.aligned.m16n8k16.row.col.f32.bf16.bf16.f32 "
        "{%0,%1,%2,%3}, {%4,%5,%6,%7}, {%8,%9}, {%0,%1,%2,%3};"
        : "+f"(d[0]), "+f"(d[1]), "+f"(d[2]), "+f"(d[3])
        : "r"(a[0]), "r"(a[1]), "r"(a[2]), "r"(a[3]), "r"(b0), "r"(b1));
}
// exp on FMA pipe: exp(x) = 2^(x*log2e), degree-6 poly, exponent bit-add
__device__ __forceinline__ float fexp(float x) {
    float y = x * 1.4426950408889634f;
    int k = __float2int_rn(y);
    float f = y - (float)k;
    float p = 1.5403530393381610e-4f;
    p = p * f + 1.3333558146428443e-3f;
    p = p * f + 9.6181291076284772e-3f;
    p = p * f + 5.5504108664821580e-2f;
    p = p * f + 2.4022650695910071e-1f;
    p = p * f + 6.9314718055994531e-1f;
    p = p * f + 1.0f;
    return __int_as_float(__float_as_int(p) + (k << 23));
}
__device__ __forceinline__ uint32_t resid_pack(uint32_t hp, float a, float b) {
    float ha = __uint_as_float(hp << 16);
    float hb = __uint_as_float(hp & 0xFFFF0000u);
    return pack_bf16x2(a - ha, b - hb);
}

__global__ void zero_state() {
    int i = blockIdx.x * blockDim.x + threadIdx.x;
    if (i < BB*HW*CO) g_c[i] = 0.f;
    if (i < BB*HW*8) {
        uint4 z = make_uint4(0, 0, 0, 0);
        g_hhi[i] = z; g_hlo[i] = z;
    }
}

__device__ __forceinline__ float sigm(float x) { return 1.f / (1.f + __expf(-x)); }

// ---------------------------------------------------------------------------
// One-time preps
// ---------------------------------------------------------------------------
__global__ void prep_weights(const float* __restrict__ conv_w) {
    int idx = blockIdx.x * blockDim.x + threadIdx.x;
    if (idx >= 18*16384) return;
    int k     = idx & 63;
    int oc    = (idx >> 6) & 255;
    int chunk = idx >> 14;
    int tap = chunk >> 1, half = chunk & 1;
    int ci  = half * 64 + k;
    float w = conv_w[(oc*128 + ci)*9 + tap];
    __nv_bfloat16 hi = __float2bfloat16_rn(w);
    __nv_bfloat16 lo = __float2bfloat16_rn(w - __bfloat162float(hi));
    g_wp[(size_t)(chunk*2 + 0)*16384 + oc*64 + k] = hi;
    g_wp[(size_t)(chunk*2 + 1)*16384 + oc*64 + k] = lo;
}

__global__ void prep_peep(const float* __restrict__ Wci,
                          const float* __restrict__ Wcf,
                          const float* __restrict__ Wco) {
    int idx = blockIdx.x * blockDim.x + threadIdx.x;
    if (idx >= 3*CO*HW) return;
    int w = idx >> 16;
    int rem = idx & 65535;
    int c = rem >> 10, pix = rem & 1023;
    const float* src = (w == 0) ? Wci : (w == 1) ? Wcf : Wco;
    g_peep[((size_t)w*HW + pix)*CO + c] = src[c*HW + pix];
}

__global__ void prep_zw(const float* __restrict__ zw) {
    int idx = blockIdx.x * blockDim.x + threadIdx.x;
    if (idx >= 2048) return;
    int co = idx >> 5, cp = idx & 31;
    float a = zw[co*64 + 2*cp], b = zw[co*64 + 2*cp + 1];
    uint32_t hp = pack_bf16x2(a, b);
    g_zwh32[idx] = hp;
    g_zwl32[idx] = resid_pack(hp, a, b);
}

// X transpose + hi/lo split: [b][ci][t][pix] f32 -> [b][t][pix][ci] bf16 x2
__global__ __launch_bounds__(256) void prep_x(const float* __restrict__ X) {
    __shared__ float tile[64][133];
    const int tid = threadIdx.x;
    const int p0 = blockIdx.x * 128;
    const int t = blockIdx.y, b = blockIdx.z;
    for (int i = tid; i < 64*128; i += 256) {
        int ci = i >> 7, p = i & 127;
        tile[ci][p] = X[((size_t)(b*64 + ci)*16 + t)*1024 + p0 + p];
    }
    __syncthreads();
    for (int i = tid; i < 1024; i += 256) {
        int p = i >> 3, q = i & 7;
        uint32_t hi[4], lo[4];
#pragma unroll
        for (int j = 0; j < 4; j++) {
            float a = tile[q*8 + 2*j][p], bv = tile[q*8 + 2*j + 1][p];
            uint32_t hp = pack_bf16x2(a, bv);
            hi[j] = hp;
            lo[j] = resid_pack(hp, a, bv);
        }
        size_t o = ((size_t)(b*TT + t)*HW + p0 + p)*8 + q;
        g_xhi[o] = make_uint4(hi[0], hi[1], hi[2], hi[3]);
        g_xlo[o] = make_uint4(lo[0], lo[1], lo[2], lo[3]);
    }
}

// ---------------------------------------------------------------------------
// Conv as implicit GEMM on mma.sync bf16 (hi/lo 3-term split).
// ---------------------------------------------------------------------------
#define PR 144
#define OFF_A_HI 0
#define OFF_A_LO 29376
#define OFF_B_HI 58752
#define OFF_B_LO 77184
#define CONV_SMEM 95616

__global__ __launch_bounds__(256) void conv_mma_kernel(int t)
{
    extern __shared__ char sm[];
    const uint32_t sb = smem_u32(sm);
    const int tid = threadIdx.x;
    const int lane = tid & 31, warp = tid >> 5;
    const int tile = blockIdx.x, b = blockIdx.y, nhalf = blockIdx.z;
    const int r0 = tile * 4;
    const int warpM = (warp & 3) * 32;
    const int warpN = (warp >> 2) * 64;

    float acc[2][8][4];
#pragma unroll
    for (int mt = 0; mt < 2; mt++)
#pragma unroll
        for (int nt = 0; nt < 8; nt++)
#pragma unroll
            for (int i = 0; i < 4; i++) acc[mt][nt][i] = 0.f;

    int aofs[2];
    {
        int m_off = (lane & 7) + ((lane >> 3) & 1) * 8;
        int kb = (lane >> 4) * 16;
#pragma unroll
        for (int mt = 0; mt < 2; mt++) {
            int m = warpM + mt*16 + m_off;
            int hp = ((m >> 5) + 1)*34 + (m & 31) + 1;
            aofs[mt] = hp*PR + kb;
        }
    }
    const uint32_t boff = ((lane & 7) + (lane >> 4) * 8) * PR
                        + ((lane >> 3) & 1) * 16 + warpN*PR;

    for (int half = 0; half < 2; half++) {
        {
            const uint4* shi; const uint4* slo;
            if (half == 0) {
                shi = g_xhi + (size_t)(b*TT + t)*HW*8;
                slo = g_xlo + (size_t)(b*TT + t)*HW*8;
            } else {
                shi = g_hhi + (size_t)b*HW*8;
                slo = g_hlo + (size_t)b*HW*8;
            }
#pragma unroll 2
            for (int i = tid; i < 1632; i += 256) {
                int pix = i >> 3, q = i & 7;
                int hr = pix / 34, hc = pix - hr*34;
                int gr = r0 + hr - 1, gc = hc - 1;
                uint4 vhi = make_uint4(0,0,0,0), vlo = vhi;
                if (gr >= 0 && gr < 32 && gc >= 0 && gc < 32) {
                    int gp = gr*32 + gc;
                    vhi = shi[gp*8 + q];
                    vlo = slo[gp*8 + q];
                }
                *(uint4*)(sm + OFF_A_HI + pix*PR + q*16) = vhi;
                *(uint4*)(sm + OFF_A_LO + pix*PR + q*16) = vlo;
            }
        }

        for (int tap = 0; tap < 9; tap++) {
            const int dr = tap/3 - 1, dc = tap%3 - 1;
            const int tapd = (dr*34 + dc)*PR;
            {
                const uint4* wsrc = (const uint4*)g_wp
                    + (size_t)(tap*2 + half)*4096 + nhalf*1024;
#pragma unroll 2
                for (int i = tid; i < 2048; i += 256) {
                    int term = i >> 10, r = (i >> 3) & 127, q = i & 7;
                    uint4 v = wsrc[term*2048 + r*8 + q];
                    *(uint4*)(sm + (term ? OFF_B_LO : OFF_B_HI) + r*PR + q*16) = v;
                }
            }
            __syncthreads();

#pragma unroll
            for (int ks = 0; ks < 4; ks++) {
                uint32_t ah[2][4], al[2][4];
#pragma unroll
                for (int mt = 0; mt < 2; mt++) {
                    ldsm_x4(sb + OFF_A_HI + aofs[mt] + tapd + ks*32, ah[mt]);
                    ldsm_x4(sb + OFF_A_LO + aofs[mt] + tapd + ks*32, al[mt]);
                }
#pragma unroll
                for (int ng = 0; ng < 4; ng++) {
                    uint32_t bh[4], bl[4];
                    ldsm_x4(sb + OFF_B_HI + boff + ng*(16*PR) + ks*32, bh);
                    ldsm_x4(sb + OFF_B_LO + boff + ng*(16*PR) + ks*32, bl);
#pragma unroll
                    for (int mt = 0; mt < 2; mt++) {
                        mma_bf16(acc[mt][2*ng],   ah[mt], bh[0], bh[1]);
                        mma_bf16(acc[mt][2*ng+1], ah[mt], bh[2], bh[3]);
                        mma_bf16(acc[mt][2*ng],   al[mt], bh[0], bh[1]);
                        mma_bf16(acc[mt][2*ng+1], al[mt], bh[2], bh[3]);
                        mma_bf16(acc[mt][2*ng],   ah[mt], bl[0], bl[1]);
                        mma_bf16(acc[mt][2*ng+1], ah[mt], bl[2], bl[3]);
                    }
                }
            }
            __syncthreads();
        }
    }

    {
        const int rbase = tile*128 + warpM + (lane >> 2);
        const int cbase = nhalf*128 + warpN + 2*(lane & 3);
        float* gout = g_conv + (size_t)b*HW*256;
#pragma unroll
        for (int mt = 0; mt < 2; mt++) {
#pragma unroll
            for (int nt = 0; nt < 8; nt++) {
                int pix = rbase + mt*16;
                int oc  = cbase + nt*8;
                *(float2*)(gout + (size_t)pix*256 + oc) =
                    make_float2(acc[mt][nt][0], acc[mt][nt][1]);
                *(float2*)(gout + (size_t)(pix + 8)*256 + oc) =
                    make_float2(acc[mt][nt][2], acc[mt][nt][3]);
            }
        }
    }
}

// ---------------------------------------------------------------------------
// Elementwise LSTM gates (wide grid — R9 form).
// ---------------------------------------------------------------------------
__global__ __launch_bounds__(256) void gates_kernel(const float* __restrict__ conv_b)
{
    int idx = blockIdx.x * blockDim.x + threadIdx.x;
    int c   = idx & 63;
    int pix = (idx >> 6) & 1023;
    int b   = idx >> 16;
    size_t row = ((size_t)b*HW + pix)*256;
    float ic = g_conv[row + c];
    float fc = g_conv[row + 64 + c];
    float gc = g_conv[row + 128 + c];
    float oc = g_conv[row + 192 + c];
    size_t ci = ((size_t)b*HW + pix)*CO + c;
    float cold = g_c[ci];
    size_t pp = (size_t)pix*CO + c;
    float iG = sigm(ic + conv_b[c]       + g_peep[pp] * cold);
    float fG = sigm(fc + conv_b[64 + c]  + g_peep[(size_t)HW*CO + pp] * cold);
    float nc = fG * cold + iG * tanhf(gc + conv_b[128 + c]);
    float oG = sigm(oc + conv_b[192 + c] + g_peep[(size_t)2*HW*CO + pp] * nc);
    g_c[ci]  = nc;
    g_hn[ci] = oG * tanhf(nc);
}

// ---------------------------------------------------------------------------
// qkv GEMM + fused bf16 hi/lo pack. Grid (8 pixel-tiles, B), 256 threads.
// Lane owns 4 consecutive pixels (float4 LDS). Epilogue packs q/k (in-thread
// j-pairs) and v (in-thread m-pairs) directly from registers.
// ---------------------------------------------------------------------------
#define QKVP_SMEM ((64*132 + 96*64 + 96) * 4)

__global__ __launch_bounds__(256) void qkvp_kernel(
    const float* __restrict__ qw, const float* __restrict__ qb,
    const float* __restrict__ kw, const float* __restrict__ kb,
    const float* __restrict__ vw, const float* __restrict__ vb)
{
    extern __shared__ float smf[];
    float* s_h = smf;                    // [64][132]
    float* s_w = smf + 64*132;           // [96][64]
    float* s_b = smf + 64*132 + 96*64;   // [96]

    const int tid = threadIdx.x;
    const int b  = blockIdx.y;
    const int p0 = blockIdx.x * 128;

    for (int idx = tid; idx < 96*64; idx += 256) {
        int r = idx >> 6, c = idx & 63;
        float v;
        if (r < 16)      v = qw[r*64 + c];
        else if (r < 32) v = kw[(r - 16)*64 + c];
        else             v = vw[(r - 32)*64 + c];
        s_w[idx] = v;
    }
    if (tid < 96) s_b[tid] = (tid < 16) ? qb[tid]
                            : (tid < 32) ? kb[tid - 16] : vb[tid - 32];
    // stage h_n transposed into smem
    for (int idx = tid; idx < 8192; idx += 256) {
        int p = idx >> 6, c = idx & 63;
        s_h[c*132 + p] = g_hn[((size_t)b*HW + p0 + p)*CO + c];
    }
    __syncthreads();

    const int lane = tid & 31, grp = tid >> 5;
    float acc[12][4];
#pragma unroll
    for (int rl = 0; rl < 12; rl++)
#pragma unroll
        for (int p = 0; p < 4; p++) acc[rl][p] = 0.f;

    for (int c = 0; c < 64; c++) {
        float4 hv = *(const float4*)(s_h + c*132 + lane*4);
#pragma unroll
        for (int rl = 0; rl < 12; rl++) {
            float wv = s_w[(grp*12 + rl)*64 + c];
            acc[rl][0] += wv * hv.x;
            acc[rl][1] += wv * hv.y;
            acc[rl][2] += wv * hv.z;
            acc[rl][3] += wv * hv.w;
        }
    }

    const int n0 = p0 + lane*4;
#pragma unroll
    for (int rl = 0; rl < 12; rl++) {
        float bia = s_b[grp*12 + rl];
#pragma unroll
        for (int p = 0; p < 4; p++) acc[rl][p] += bia;
    }
#pragma unroll
    for (int rl = 0; rl < 12; rl++) {
        int r = grp*12 + rl;
        if (r < 32) {
            if ((r & 1) == 0) {
                uint32_t* dh = (uint32_t*)((r < 16) ? g_qh : g_kh);
                uint32_t* dl = (uint32_t*)((r < 16) ? g_ql : g_kl);
                int jp = (r & 15) >> 1;
#pragma unroll
                for (int p = 0; p < 4; p++) {
                    float a = acc[rl][p], c2 = acc[rl + 1][p];
                    uint32_t hp = pack_bf16x2(a, c2);
                    size_t o = ((size_t)b*HW + n0 + p)*8 + jp;
                    dh[o] = hp;
                    dl[o] = resid_pack(hp, a, c2);
                }
            }
        } else {
            int c = r - 32;
            size_t o = ((size_t)(b*CO + c))*512 + (n0 >> 1);
            uint32_t h0 = pack_bf16x2(acc[rl][0], acc[rl][1]);
            uint32_t h1 = pack_bf16x2(acc[rl][2], acc[rl][3]);
            g_vh32[o]     = h0;
            g_vl32[o]     = resid_pack(h0, acc[rl][0], acc[rl][1]);
            g_vh32[o + 1] = h1;
            g_vl32[o + 1] = resid_pack(h1, acc[rl][2], acc[rl][3]);
        }
    }
}

// ---------------------------------------------------------------------------
// MMA attention + fused z-projection. (unchanged from R9)
// ---------------------------------------------------------------------------
#define AQH 0
#define AQL 6144
#define AKH 12288
#define AKL 18432
#define AVH 24576
#define AVL 41984
#define AZH 59392
#define AZL 68608
#define ATTN2_SMEM 77824

__global__ __launch_bounds__(256) void attn_mma(
    const float* __restrict__ zb, float* __restrict__ out, int tstep)
{
    extern __shared__ char sm[];
    const uint32_t sbase = smem_u32(sm);
    const int tid = threadIdx.x, lane = tid & 31, warp = tid >> 5;
    const int b = blockIdx.y, tile = blockIdx.x;
    const int n0 = tile * 128;

    {
        int row = tid & 127, term = tid >> 7;
        const uint4* src = (term ? g_ql : g_qh) + ((size_t)b*HW + n0 + row)*2;
        char* dst = sm + (term ? AQL : AQH) + row*48;
        ((uint4*)dst)[0] = src[0];
        ((uint4*)dst)[1] = src[1];
    }
    for (int i = tid; i < 1024; i += 256) {
        int term = i >> 9, r = (i >> 3) & 63, q = i & 7;
        const uint4* s32 = (const uint4*)(term ? g_zwl32 : g_zwh32);
        *(uint4*)(sm + (term ? AZL : AZH) + r*144 + q*16) = s32[r*8 + q];
    }
    __syncthreads();

    uint32_t aq_hi[4], aq_lo[4];
    {
        uint32_t aaddr = sbase + AQH
            + (warp*16 + (lane & 7) + ((lane >> 3) & 1)*8)*48 + (lane >> 4)*16;
        ldsm_x4(aaddr, aq_hi);
        ldsm_x4(aaddr + (AQL - AQH), aq_lo);
    }
    const uint32_t kaddr = sbase + AKH + ((lane & 7) + (lane >> 4)*8)*48
                         + ((lane >> 3) & 1)*16;
    const uint32_t vaddr = sbase + AVH + ((lane & 7) + (lane >> 4)*8)*272
                         + ((lane >> 3) & 1)*16;
    const uint32_t zaddr = sbase + AZH + ((lane & 7) + (lane >> 4)*8)*144
                         + ((lane >> 3) & 1)*16;

    float pv[8][4];
#pragma unroll
    for (int i = 0; i < 8; i++)
#pragma unroll
        for (int j = 0; j < 4; j++) pv[i][j] = 0.f;
    float L0 = 0.f, L1 = 0.f;

    for (int mt = 0; mt < 8; mt++) {
        __syncthreads();
        {
            int row = tid & 127, term = tid >> 7;
            const uint4* src = (term ? g_kl : g_kh)
                             + ((size_t)b*HW + mt*128 + row)*2;
            char* dst = sm + (term ? AKL : AKH) + row*48;
            ((uint4*)dst)[0] = src[0];
            ((uint4*)dst)[1] = src[1];
        }
#pragma unroll 2
        for (int i = tid; i < 2048; i += 256) {
            int term = i >> 10, r = (i >> 4) & 63, q = i & 15;
            const uint4* src = (const uint4*)(term ? g_vl32 : g_vh32);
            uint4 v = src[((size_t)(b*CO) + r)*128 + mt*16 + q];
            *(uint4*)(sm + (term ? AVL : AVH) + r*272 + q*16) = v;
        }
        __syncthreads();

        float sacc[16][4];
#pragma unroll
        for (int i = 0; i < 16; i++)
#pragma unroll
            for (int j = 0; j < 4; j++) sacc[i][j] = 0.f;
#pragma unroll
        for (int mg = 0; mg < 8; mg++) {
            uint32_t bh[4], bl[4];
            ldsm_x4(kaddr + mg*(16*48), bh);
            ldsm_x4(kaddr + (AKL - AKH) + mg*(16*48), bl);
            mma_bf16(sacc[2*mg],   aq_hi, bh[0], bh[1]);
            mma_bf16(sacc[2*mg+1], aq_hi, bh[2], bh[3]);
            mma_bf16(sacc[2*mg],   aq_lo, bh[0], bh[1]);
            mma_bf16(sacc[2*mg+1], aq_lo, bh[2], bh[3]);
            mma_bf16(sacc[2*mg],   aq_hi, bl[0], bl[1]);
            mma_bf16(sacc[2*mg+1], aq_hi, bl[2], bl[3]);
        }

#pragma unroll
        for (int j = 0; j < 8; j++) {
            float e0 = fexp(sacc[2*j][0]),   e1 = fexp(sacc[2*j][1]);
            float e2 = fexp(sacc[2*j][2]),   e3 = fexp(sacc[2*j][3]);
            float e4 = fexp(sacc[2*j+1][0]), e5 = fexp(sacc[2*j+1][1]);
            float e6 = fexp(sacc[2*j+1][2]), e7 = fexp(sacc[2*j+1][3]);
            L0 += e0 + e1 + e4 + e5;
            L1 += e2 + e3 + e6 + e7;
            uint32_t ah[4], al[4];
            ah[0] = pack_bf16x2(e0, e1); al[0] = resid_pack(ah[0], e0, e1);
            ah[1] = pack_bf16x2(e2, e3); al[1] = resid_pack(ah[1], e2, e3);
            ah[2] = pack_bf16x2(e4, e5); al[2] = resid_pack(ah[2], e4, e5);
            ah[3] = pack_bf16x2(e6, e7); al[3] = resid_pack(ah[3], e6, e7);
#pragma unroll
            for (int cg = 0; cg < 4; cg++) {
                uint32_t vh[4], vl[4];
                ldsm_x4(vaddr + cg*(16*272) + j*32, vh);
                ldsm_x4(vaddr + (AVL - AVH) + cg*(16*272) + j*32, vl);
                mma_bf16(pv[2*cg],   ah, vh[0], vh[1]);
                mma_bf16(pv[2*cg+1], ah, vh[2], vh[3]);
                mma_bf16(pv[2*cg],   al, vh[0], vh[1]);
                mma_bf16(pv[2*cg+1], al, vh[2], vh[3]);
                mma_bf16(pv[2*cg],   ah, vl[0], vl[1]);
                mma_bf16(pv[2*cg+1], ah, vl[2], vl[3]);
            }
        }
    }

    L0 += __shfl_xor_sync(0xFFFFFFFFu, L0, 1);
    L0 += __shfl_xor_sync(0xFFFFFFFFu, L0, 2);
    L1 += __shfl_xor_sync(0xFFFFFFFFu, L1, 1);
    L1 += __shfl_xor_sync(0xFFFFFFFFu, L1, 2);
    float inv0 = 1.f / L0, inv1 = 1.f / L1;

    float zp[8][4];
#pragma unroll
    for (int i = 0; i < 8; i++)
#pragma unroll
        for (int j = 0; j < 4; j++) zp[i][j] = 0.f;
#pragma unroll
    for (int ck = 0; ck < 4; ck++) {
        uint32_t ah[4], al[4];
        ah[0] = pack_bf16x2(pv[2*ck][0], pv[2*ck][1]);
        al[0] = resid_pack(ah[0], pv[2*ck][0], pv[2*ck][1]);
        ah[1] = pack_bf16x2(pv[2*ck][2], pv[2*ck][3]);
        al[1] = resid_pack(ah[1], pv[2*ck][2], pv[2*ck][3]);
        ah[2] = pack_bf16x2(pv[2*ck+1][0], pv[2*ck+1][1]);
        al[2] = resid_pack(ah[2], pv[2*ck+1][0], pv[2*ck+1][1]);
        ah[3] = pack_bf16x2(pv[2*ck+1][2], pv[2*ck+1][3]);
        al[3] = resid_pack(ah[3], pv[2*ck+1][2], pv[2*ck+1][3]);
#pragma unroll
        for (int cog = 0; cog < 4; cog++) {
            uint32_t bh[4], bl[4];
            ldsm_x4(zaddr + cog*(16*144) + ck*32, bh);
            ldsm_x4(zaddr + (AZL - AZH) + cog*(16*144) + ck*32, bl);
            mma_bf16(zp[2*cog],   ah, bh[0], bh[1]);
            mma_bf16(zp[2*cog+1], ah, bh[2], bh[3]);
            mma_bf16(zp[2*cog],   al, bh[0], bh[1]);
            mma_bf16(zp[2*cog+1], al, bh[2], bh[3]);
            mma_bf16(zp[2*cog],   ah, bl[0], bl[1]);
            mma_bf16(zp[2*cog+1], ah, bl[2], bl[3]);
        }
    }

    {
        const int r0 = warp*16 + (lane >> 2);
        const int pix = n0 + r0;
        uint32_t* hh = (uint32_t*)g_hhi + ((size_t)b*HW + pix)*32;
        uint32_t* hl = (uint32_t*)g_hlo + ((size_t)b*HW + pix)*32;
#pragma unroll
        for (int cog = 0; cog < 4; cog++) {
#pragma unroll
            for (int tt = 0; tt < 2; tt++) {
                int co = cog*16 + tt*8 + 2*(lane & 3);
                float bz0 = __ldg(zb + co), bz1 = __ldg(zb + co + 1);
                float v0 = zp[2*cog+tt][0]*inv0 + bz0;
                float v1 = zp[2*cog+tt][1]*inv0 + bz1;
                float v2 = zp[2*cog+tt][2]*inv1 + bz0;
                float v3 = zp[2*cog+tt][3]*inv1 + bz1;
                size_t o0 = ((size_t)(b*CO + co)*TT + tstep)*HW;
                size_t o1 = ((size_t)(b*CO + co + 1)*TT + tstep)*HW;
                out[o0 + pix]     = v0;
                out[o1 + pix]     = v1;
                out[o0 + pix + 8] = v2;
                out[o1 + pix + 8] = v3;
                int ci = cog*8 + tt*4 + (lane & 3);
                uint32_t hp0 = pack_bf16x2(v0, v1);
                hh[ci] = hp0;
                hl[ci] = resid_pack(hp0, v0, v1);
                uint32_t hp1 = pack_bf16x2(v2, v3);
                hh[256 + ci] = hp1;
                hl[256 + ci] = resid_pack(hp1, v2, v3);
            }
        }
    }
}

// ---------------------------------------------------------------------------
extern "C" void kernel_launch(void* const* d_in, const int* in_sizes, int n_in,
                              void* d_out, int out_size)
{
    (void)in_sizes; (void)n_in; (void)out_size;
    const float* X      = (const float*)d_in[0];
    const float* conv_w = (const float*)d_in[1];
    const float* conv_b = (const float*)d_in[2];
    const float* W_ci   = (const float*)d_in[3];
    const float* W_cf   = (const float*)d_in[4];
    const float* W_co   = (const float*)d_in[5];
    const float* q_w    = (const float*)d_in[6];
    const float* q_b    = (const float*)d_in[7];
    const float* k_w    = (const float*)d_in[8];
    const float* k_b    = (const float*)d_in[9];
    const float* v_w    = (const float*)d_in[10];
    const float* v_b    = (const float*)d_in[11];
    const float* z_w    = (const float*)d_in[12];
    const float* z_b    = (const float*)d_in[13];
    float* out = (float*)d_out;

    cudaFuncSetAttribute(conv_mma_kernel,
        cudaFuncAttributeMaxDynamicSharedMemorySize, CONV_SMEM);
    cudaFuncSetAttribute(qkvp_kernel,
        cudaFuncAttributeMaxDynamicSharedMemorySize, QKVP_SMEM);
    cudaFuncSetAttribute(attn_mma,
        cudaFuncAttributeMaxDynamicSharedMemorySize, ATTN2_SMEM);

    zero_state<<<(BB*HW*CO + 255)/256, 256>>>();
    prep_weights<<<(18*16384 + 255)/256, 256>>>(conv_w);
    prep_peep<<<(3*CO*HW + 255)/256, 256>>>(W_ci, W_cf, W_co);
    prep_zw<<<8, 256>>>(z_w);
    prep_x<<<dim3(8, TT, BB), 256>>>(X);

    for (int t = 0; t < TT; t++) {
        conv_mma_kernel<<<dim3(8, BB, 2), 256, CONV_SMEM>>>(t);
        gates_kernel<<<(BB*HW*CO + 255)/256, 256>>>(conv_b);
        qkvp_kernel<<<dim3(8, BB), 256, QKVP_SMEM>>>(
            q_w, q_b, k_w, k_b, v_w, v_b);
        attn_mma<<<dim3(8, BB), 256, ATTN2_SMEM>>>(z_b, out, t);
    }
}

// round 14
// speedup vs baseline: 1.1872x; 1.0797x over previous
#include <cuda_runtime.h>
#include <cuda_bf16.h>
#include <math.h>
#include <stdint.h>

#define BB   16
#define CIN  64
#define CO   64
#define HIDD 16
#define TT   16
#define HW   1024

// ---------------------------------------------------------------------------
// Persistent device scratch (allocation-free)
// ---------------------------------------------------------------------------
__device__ float g_c [BB*HW*CO];            // cell state, layout [b][pix][c]
__device__ float g_hn[BB*HW*CO];            // new_h,      layout [b][pix][c]
__device__ float g_q [BB*HIDD*HW];          // [b][j][n] fp32
__device__ float g_k [BB*HIDD*HW];
__device__ float g_v [BB*CO*HW];
__device__ float g_conv[BB*HW*256];         // conv out, layout [b][pix][oc256]
__device__ float g_convX[(size_t)BB*TT*HW*256]; // X-half partial sums
__device__ __nv_bfloat16 g_wp[18*2*16384];  // conv weights hi/lo
__device__ float g_peep[3*HW*CO];           // peepholes transposed [w][pix][c]
// pre-split bf16 conv inputs, rows of 64 bf16 = 8 uint4
__device__ uint4 g_xhi[BB*TT*HW*8];         // X hi, [b][t][pix][ci]
__device__ uint4 g_xlo[BB*TT*HW*8];
__device__ uint4 g_hhi[BB*HW*8];            // h hi, [b][pix][ci]
__device__ uint4 g_hlo[BB*HW*8];
// packed attention operands (bf16 hi/lo)
__device__ uint4 g_qh[BB*HW*2];             // q [b][n][j16]
__device__ uint4 g_ql[BB*HW*2];
__device__ uint4 g_kh[BB*HW*2];             // k [b][m][j16]
__device__ uint4 g_kl[BB*HW*2];
__device__ uint32_t g_vh32[BB*CO*512];      // v [b][c][m-pairs]
__device__ uint32_t g_vl32[BB*CO*512];
__device__ uint32_t g_zwh32[2048];          // zw [co][c]
__device__ uint32_t g_zwl32[2048];

__device__ __forceinline__ uint32_t smem_u32(const void* p) {
    uint32_t a;
    asm("{ .reg .u64 t; cvta.to.shared.u64 t, %1; cvt.u32.u64 %0, t; }"
        : "=r"(a) : "l"(p));
    return a;
}
__device__ __forceinline__ uint32_t pack_bf16x2(float lo, float hi) {
    uint32_t r;
    asm("cvt.rn.bf16x2.f32 %0, %1, %2;" : "=r"(r) : "f"(hi), "f"(lo));
    return r;
}
__device__ __forceinline__ void ldsm_x4(uint32_t addr, uint32_t r[4]) {
    asm volatile("ldmatrix.sync.aligned.m8n8.x4.shared.b16 {%0,%1,%2,%3}, [%4];"
        : "=r"(r[0]), "=r"(r[1]), "=r"(r[2]), "=r"(r[3]) : "r"(addr));
}
__device__ __forceinline__ void mma_bf16(float d[4], const uint32_t a[4],
                                         uint32_t b0, uint32_t b1) {
    asm volatile("mma.sync.aligned.m16n8k16.row.col.f32.bf16.bf16.f32 "
        "{%0,%1,%2,%3}, {%4,%5,%6,%7}, {%8,%9}, {%0,%1,%2,%3};"
        : "+f"(d[0]), "+f"(d[1]), "+f"(d[2]), "+f"(d[3])
        : "r"(a[0]), "r"(a[1]), "r"(a[2]), "r"(a[3]), "r"(b0), "r"(b1));
}
// exp on FMA pipe: exp(x) = 2^(x*log2e), degree-6 poly, exponent bit-add
__device__ __forceinline__ float fexp(float x) {
    float y = x * 1.4426950408889634f;
    int k = __float2int_rn(y);
    float f = y - (float)k;
    float p = 1.5403530393381610e-4f;
    p = p * f + 1.3333558146428443e-3f;
    p = p * f + 9.6181291076284772e-3f;
    p = p * f + 5.5504108664821580e-2f;
    p = p * f + 2.4022650695910071e-1f;
    p = p * f + 6.9314718055994531e-1f;
    p = p * f + 1.0f;
    return __int_as_float(__float_as_int(p) + (k << 23));
}
__device__ __forceinline__ uint32_t resid_pack(uint32_t hp, float a, float b) {
    float ha = __uint_as_float(hp << 16);
    float hb = __uint_as_float(hp & 0xFFFF0000u);
    return pack_bf16x2(a - ha, b - hb);
}

__global__ void zero_state() {
    int i = blockIdx.x * blockDim.x + threadIdx.x;
    if (i < BB*HW*CO) g_c[i] = 0.f;
    if (i < BB*HW*8) {
        uint4 z = make_uint4(0, 0, 0, 0);
        g_hhi[i] = z; g_hlo[i] = z;
    }
}

__device__ __forceinline__ float sigm(float x) { return 1.f / (1.f + __expf(-x)); }

// ---------------------------------------------------------------------------
// One-time preps
// ---------------------------------------------------------------------------
__global__ void prep_weights(const float* __restrict__ conv_w) {
    int idx = blockIdx.x * blockDim.x + threadIdx.x;
    if (idx >= 18*16384) return;
    int k     = idx & 63;
    int oc    = (idx >> 6) & 255;
    int chunk = idx >> 14;
    int tap = chunk >> 1, half = chunk & 1;
    int ci  = half * 64 + k;
    float w = conv_w[(oc*128 + ci)*9 + tap];
    __nv_bfloat16 hi = __float2bfloat16_rn(w);
    __nv_bfloat16 lo = __float2bfloat16_rn(w - __bfloat162float(hi));
    g_wp[(size_t)(chunk*2 + 0)*16384 + oc*64 + k] = hi;
    g_wp[(size_t)(chunk*2 + 1)*16384 + oc*64 + k] = lo;
}

__global__ void prep_peep(const float* __restrict__ Wci,
                          const float* __restrict__ Wcf,
                          const float* __restrict__ Wco) {
    int idx = blockIdx.x * blockDim.x + threadIdx.x;
    if (idx >= 3*CO*HW) return;
    int w = idx >> 16;
    int rem = idx & 65535;
    int c = rem >> 10, pix = rem & 1023;
    const float* src = (w == 0) ? Wci : (w == 1) ? Wcf : Wco;
    g_peep[((size_t)w*HW + pix)*CO + c] = src[c*HW + pix];
}

__global__ void prep_zw(const float* __restrict__ zw) {
    int idx = blockIdx.x * blockDim.x + threadIdx.x;
    if (idx >= 2048) return;
    int co = idx >> 5, cp = idx & 31;
    float a = zw[co*64 + 2*cp], b = zw[co*64 + 2*cp + 1];
    uint32_t hp = pack_bf16x2(a, b);
    g_zwh32[idx] = hp;
    g_zwl32[idx] = resid_pack(hp, a, b);
}

// X transpose + hi/lo split: [b][ci][t][pix] f32 -> [b][t][pix][ci] bf16 x2
__global__ __launch_bounds__(256) void prep_x(const float* __restrict__ X) {
    __shared__ float tile[64][133];
    const int tid = threadIdx.x;
    const int p0 = blockIdx.x * 128;
    const int t = blockIdx.y, b = blockIdx.z;
    for (int i = tid; i < 64*128; i += 256) {
        int ci = i >> 7, p = i & 127;
        tile[ci][p] = X[((size_t)(b*64 + ci)*16 + t)*1024 + p0 + p];
    }
    __syncthreads();
    for (int i = tid; i < 1024; i += 256) {
        int p = i >> 3, q = i & 7;
        uint32_t hi[4], lo[4];
#pragma unroll
        for (int j = 0; j < 4; j++) {
            float a = tile[q*8 + 2*j][p], bv = tile[q*8 + 2*j + 1][p];
            uint32_t hp = pack_bf16x2(a, bv);
            hi[j] = hp;
            lo[j] = resid_pack(hp, a, bv);
        }
        size_t o = ((size_t)(b*TT + t)*HW + p0 + p)*8 + q;
        g_xhi[o] = make_uint4(hi[0], hi[1], hi[2], hi[3]);
        g_xlo[o] = make_uint4(lo[0], lo[1], lo[2], lo[3]);
    }
}

// ---------------------------------------------------------------------------
// Conv implicit GEMM, X-half only (precomputable, runs on side stream).
// Writes fp32 partial sums to g_convX[b][t][pix][oc256].
// ---------------------------------------------------------------------------
#define PR 144
#define OFF_A_HI 0
#define OFF_A_LO 29376
#define OFF_B_HI 58752
#define OFF_B_LO 77184
#define CONV_SMEM 95616

__global__ __launch_bounds__(256) void conv_x_kernel(int t)
{
    extern __shared__ char sm[];
    const uint32_t sb = smem_u32(sm);
    const int tid = threadIdx.x;
    const int lane = tid & 31, warp = tid >> 5;
    const int tile = blockIdx.x, b = blockIdx.y, nhalf = blockIdx.z;
    const int r0 = tile * 4;
    const int warpM = (warp & 3) * 32;
    const int warpN = (warp >> 2) * 64;

    float acc[2][8][4];
#pragma unroll
    for (int mt = 0; mt < 2; mt++)
#pragma unroll
        for (int nt = 0; nt < 8; nt++)
#pragma unroll
            for (int i = 0; i < 4; i++) acc[mt][nt][i] = 0.f;

    int aofs[2];
    {
        int m_off = (lane & 7) + ((lane >> 3) & 1) * 8;
        int kb = (lane >> 4) * 16;
#pragma unroll
        for (int mt = 0; mt < 2; mt++) {
            int m = warpM + mt*16 + m_off;
            int hp = ((m >> 5) + 1)*34 + (m & 31) + 1;
            aofs[mt] = hp*PR + kb;
        }
    }
    const uint32_t boff = ((lane & 7) + (lane >> 4) * 8) * PR
                        + ((lane >> 3) & 1) * 16 + warpN*PR;

    // stage A halo (X)
    {
        const uint4* shi = g_xhi + (size_t)(b*TT + t)*HW*8;
        const uint4* slo = g_xlo + (size_t)(b*TT + t)*HW*8;
#pragma unroll 2
        for (int i = tid; i < 1632; i += 256) {
            int pix = i >> 3, q = i & 7;
            int hr = pix / 34, hc = pix - hr*34;
            int gr = r0 + hr - 1, gc = hc - 1;
            uint4 vhi = make_uint4(0,0,0,0), vlo = vhi;
            if (gr >= 0 && gr < 32 && gc >= 0 && gc < 32) {
                int gp = gr*32 + gc;
                vhi = shi[gp*8 + q];
                vlo = slo[gp*8 + q];
            }
            *(uint4*)(sm + OFF_A_HI + pix*PR + q*16) = vhi;
            *(uint4*)(sm + OFF_A_LO + pix*PR + q*16) = vlo;
        }
    }

    for (int tap = 0; tap < 9; tap++) {
        const int dr = tap/3 - 1, dc = tap%3 - 1;
        const int tapd = (dr*34 + dc)*PR;
        {
            const uint4* wsrc = (const uint4*)g_wp
                + (size_t)(tap*2 + 0)*4096 + nhalf*1024;
#pragma unroll 2
            for (int i = tid; i < 2048; i += 256) {
                int term = i >> 10, r = (i >> 3) & 127, q = i & 7;
                uint4 v = wsrc[term*2048 + r*8 + q];
                *(uint4*)(sm + (term ? OFF_B_LO : OFF_B_HI) + r*PR + q*16) = v;
            }
        }
        __syncthreads();
#pragma unroll
        for (int ks = 0; ks < 4; ks++) {
            uint32_t ah[2][4], al[2][4];
#pragma unroll
            for (int mt = 0; mt < 2; mt++) {
                ldsm_x4(sb + OFF_A_HI + aofs[mt] + tapd + ks*32, ah[mt]);
                ldsm_x4(sb + OFF_A_LO + aofs[mt] + tapd + ks*32, al[mt]);
            }
#pragma unroll
            for (int ng = 0; ng < 4; ng++) {
                uint32_t bh[4], bl[4];
                ldsm_x4(sb + OFF_B_HI + boff + ng*(16*PR) + ks*32, bh);
                ldsm_x4(sb + OFF_B_LO + boff + ng*(16*PR) + ks*32, bl);
#pragma unroll
                for (int mt = 0; mt < 2; mt++) {
                    mma_bf16(acc[mt][2*ng],   ah[mt], bh[0], bh[1]);
                    mma_bf16(acc[mt][2*ng+1], ah[mt], bh[2], bh[3]);
                    mma_bf16(acc[mt][2*ng],   al[mt], bh[0], bh[1]);
                    mma_bf16(acc[mt][2*ng+1], al[mt], bh[2], bh[3]);
                    mma_bf16(acc[mt][2*ng],   ah[mt], bl[0], bl[1]);
                    mma_bf16(acc[mt][2*ng+1], ah[mt], bl[2], bl[3]);
                }
            }
        }
        __syncthreads();
    }

    {
        const int rbase = tile*128 + warpM + (lane >> 2);
        const int cbase = nhalf*128 + warpN + 2*(lane & 3);
        float* gout = g_convX + (size_t)(b*TT + t)*HW*256;
#pragma unroll
        for (int mt = 0; mt < 2; mt++) {
#pragma unroll
            for (int nt = 0; nt < 8; nt++) {
                int pix = rbase + mt*16;
                int oc  = cbase + nt*8;
                *(float2*)(gout + (size_t)pix*256 + oc) =
                    make_float2(acc[mt][nt][0], acc[mt][nt][1]);
                *(float2*)(gout + (size_t)(pix + 8)*256 + oc) =
                    make_float2(acc[mt][nt][2], acc[mt][nt][3]);
            }
        }
    }
}

// ---------------------------------------------------------------------------
// Conv implicit GEMM, h-half. Acc initialized from g_convX (bit-identical
// to the former fused 18-chunk loop). Writes g_conv.
// ---------------------------------------------------------------------------
__global__ __launch_bounds__(256) void conv_h_kernel(int t)
{
    extern __shared__ char sm[];
    const uint32_t sb = smem_u32(sm);
    const int tid = threadIdx.x;
    const int lane = tid & 31, warp = tid >> 5;
    const int tile = blockIdx.x, b = blockIdx.y, nhalf = blockIdx.z;
    const int r0 = tile * 4;
    const int warpM = (warp & 3) * 32;
    const int warpN = (warp >> 2) * 64;

    const int rbase = tile*128 + warpM + (lane >> 2);
    const int cbase = nhalf*128 + warpN + 2*(lane & 3);

    float acc[2][8][4];
    {   // init from X partial sums
        const float* gin = g_convX + (size_t)(b*TT + t)*HW*256;
#pragma unroll
        for (int mt = 0; mt < 2; mt++) {
#pragma unroll
            for (int nt = 0; nt < 8; nt++) {
                int pix = rbase + mt*16;
                int oc  = cbase + nt*8;
                float2 v0 = *(const float2*)(gin + (size_t)pix*256 + oc);
                float2 v1 = *(const float2*)(gin + (size_t)(pix + 8)*256 + oc);
                acc[mt][nt][0] = v0.x; acc[mt][nt][1] = v0.y;
                acc[mt][nt][2] = v1.x; acc[mt][nt][3] = v1.y;
            }
        }
    }

    int aofs[2];
    {
        int m_off = (lane & 7) + ((lane >> 3) & 1) * 8;
        int kb = (lane >> 4) * 16;
#pragma unroll
        for (int mt = 0; mt < 2; mt++) {
            int m = warpM + mt*16 + m_off;
            int hp = ((m >> 5) + 1)*34 + (m & 31) + 1;
            aofs[mt] = hp*PR + kb;
        }
    }
    const uint32_t boff = ((lane & 7) + (lane >> 4) * 8) * PR
                        + ((lane >> 3) & 1) * 16 + warpN*PR;

    // stage A halo (h)
    {
        const uint4* shi = g_hhi + (size_t)b*HW*8;
        const uint4* slo = g_hlo + (size_t)b*HW*8;
#pragma unroll 2
        for (int i = tid; i < 1632; i += 256) {
            int pix = i >> 3, q = i & 7;
            int hr = pix / 34, hc = pix - hr*34;
            int gr = r0 + hr - 1, gc = hc - 1;
            uint4 vhi = make_uint4(0,0,0,0), vlo = vhi;
            if (gr >= 0 && gr < 32 && gc >= 0 && gc < 32) {
                int gp = gr*32 + gc;
                vhi = shi[gp*8 + q];
                vlo = slo[gp*8 + q];
            }
            *(uint4*)(sm + OFF_A_HI + pix*PR + q*16) = vhi;
            *(uint4*)(sm + OFF_A_LO + pix*PR + q*16) = vlo;
        }
    }

    for (int tap = 0; tap < 9; tap++) {
        const int dr = tap/3 - 1, dc = tap%3 - 1;
        const int tapd = (dr*34 + dc)*PR;
        {
            const uint4* wsrc = (const uint4*)g_wp
                + (size_t)(tap*2 + 1)*4096 + nhalf*1024;
#pragma unroll 2
            for (int i = tid; i < 2048; i += 256) {
                int term = i >> 10, r = (i >> 3) & 127, q = i & 7;
                uint4 v = wsrc[term*2048 + r*8 + q];
                *(uint4*)(sm + (term ? OFF_B_LO : OFF_B_HI) + r*PR + q*16) = v;
            }
        }
        __syncthreads();
#pragma unroll
        for (int ks = 0; ks < 4; ks++) {
            uint32_t ah[2][4], al[2][4];
#pragma unroll
            for (int mt = 0; mt < 2; mt++) {
                ldsm_x4(sb + OFF_A_HI + aofs[mt] + tapd + ks*32, ah[mt]);
                ldsm_x4(sb + OFF_A_LO + aofs[mt] + tapd + ks*32, al[mt]);
            }
#pragma unroll
            for (int ng = 0; ng < 4; ng++) {
                uint32_t bh[4], bl[4];
                ldsm_x4(sb + OFF_B_HI + boff + ng*(16*PR) + ks*32, bh);
                ldsm_x4(sb + OFF_B_LO + boff + ng*(16*PR) + ks*32, bl);
#pragma unroll
                for (int mt = 0; mt < 2; mt++) {
                    mma_bf16(acc[mt][2*ng],   ah[mt], bh[0], bh[1]);
                    mma_bf16(acc[mt][2*ng+1], ah[mt], bh[2], bh[3]);
                    mma_bf16(acc[mt][2*ng],   al[mt], bh[0], bh[1]);
                    mma_bf16(acc[mt][2*ng+1], al[mt], bh[2], bh[3]);
                    mma_bf16(acc[mt][2*ng],   ah[mt], bl[0], bl[1]);
                    mma_bf16(acc[mt][2*ng+1], ah[mt], bl[2], bl[3]);
                }
            }
        }
        __syncthreads();
    }

    {
        float* gout = g_conv + (size_t)b*HW*256;
#pragma unroll
        for (int mt = 0; mt < 2; mt++) {
#pragma unroll
            for (int nt = 0; nt < 8; nt++) {
                int pix = rbase + mt*16;
                int oc  = cbase + nt*8;
                *(float2*)(gout + (size_t)pix*256 + oc) =
                    make_float2(acc[mt][nt][0], acc[mt][nt][1]);
                *(float2*)(gout + (size_t)(pix + 8)*256 + oc) =
                    make_float2(acc[mt][nt][2], acc[mt][nt][3]);
            }
        }
    }
}

// ---------------------------------------------------------------------------
// Elementwise LSTM gates (wide grid — R9 form).
// ---------------------------------------------------------------------------
__global__ __launch_bounds__(256) void gates_kernel(const float* __restrict__ conv_b)
{
    int idx = blockIdx.x * blockDim.x + threadIdx.x;
    int c   = idx & 63;
    int pix = (idx >> 6) & 1023;
    int b   = idx >> 16;
    size_t row = ((size_t)b*HW + pix)*256;
    float ic = g_conv[row + c];
    float fc = g_conv[row + 64 + c];
    float gc = g_conv[row + 128 + c];
    float oc = g_conv[row + 192 + c];
    size_t ci = ((size_t)b*HW + pix)*CO + c;
    float cold = g_c[ci];
    size_t pp = (size_t)pix*CO + c;
    float iG = sigm(ic + conv_b[c]       + g_peep[pp] * cold);
    float fG = sigm(fc + conv_b[64 + c]  + g_peep[(size_t)HW*CO + pp] * cold);
    float nc = fG * cold + iG * tanhf(gc + conv_b[128 + c]);
    float oG = sigm(oc + conv_b[192 + c] + g_peep[(size_t)2*HW*CO + pp] * nc);
    g_c[ci]  = nc;
    g_hn[ci] = oG * tanhf(nc);
}

// ---------------------------------------------------------------------------
// q,k,v 1x1 convs from g_hn ([b][pix][c]). Grid (8, B), 256 threads. (R9)
// ---------------------------------------------------------------------------
#define QKV_SMEM_FLOATS (64*129 + 96*64 + 96)
#define QKV_SMEM (QKV_SMEM_FLOATS * 4)

__global__ __launch_bounds__(256) void qkv_kernel(
    const float* __restrict__ qw, const float* __restrict__ qb,
    const float* __restrict__ kw, const float* __restrict__ kb,
    const float* __restrict__ vw, const float* __restrict__ vb)
{
    extern __shared__ float smf[];
    float* s_h = smf;
    float* s_w = smf + 64*129;
    float* s_b = smf + 64*129 + 96*64;

    const int tid = threadIdx.x;
    const int b  = blockIdx.y;
    const int p0 = blockIdx.x * 128;

    for (int idx = tid; idx < 8192; idx += 256) {
        int p = idx >> 6, c = idx & 63;
        s_h[c*129 + p] = g_hn[((size_t)b*HW + p0 + p)*CO + c];
    }
    for (int idx = tid; idx < 96*64; idx += 256) {
        int r = idx >> 6, c = idx & 63;
        float v;
        if (r < 16)      v = qw[r*64 + c];
        else if (r < 32) v = kw[(r - 16)*64 + c];
        else             v = vw[(r - 32)*64 + c];
        s_w[idx] = v;
    }
    if (tid < 96) s_b[tid] = (tid < 16) ? qb[tid]
                            : (tid < 32) ? kb[tid - 16] : vb[tid - 32];
    __syncthreads();

    const int lane = tid & 31, grp = tid >> 5;
    float acc[12][4];
#pragma unroll
    for (int rl = 0; rl < 12; rl++)
#pragma unroll
        for (int p = 0; p < 4; p++) acc[rl][p] = 0.f;

    for (int c = 0; c < 64; c++) {
        float hv[4];
#pragma unroll
        for (int p = 0; p < 4; p++) hv[p] = s_h[c*129 + lane + p*32];
#pragma unroll
        for (int rl = 0; rl < 12; rl++) {
            float wv = s_w[(grp*12 + rl)*64 + c];
#pragma unroll
            for (int p = 0; p < 4; p++) acc[rl][p] += wv * hv[p];
        }
    }

#pragma unroll
    for (int rl = 0; rl < 12; rl++) {
        int r = grp*12 + rl;
        float bia = s_b[r];
#pragma unroll
        for (int p = 0; p < 4; p++) {
            int n = p0 + lane + p*32;
            float v = acc[rl][p] + bia;
            if (r < 16)      g_q[(b*HIDD + r)*HW + n] = v;
            else if (r < 32) g_k[(b*HIDD + (r - 16))*HW + n] = v;
            else             g_v[(b*CO + (r - 32))*HW + n] = v;
        }
    }
}

// ---------------------------------------------------------------------------
// Pack q,k,v into bf16 hi/lo layouts for the MMA attention. (R9)
// ---------------------------------------------------------------------------
__global__ __launch_bounds__(256) void pack_qkv()
{
    int gid = blockIdx.x * blockDim.x + threadIdx.x;
    if (gid < 32768) {
        int sel = gid >> 14;
        int r = gid & 16383;
        int b = r >> 10, n = r & 1023;
        const float* src = (sel ? g_k : g_q) + (size_t)b*HIDD*HW + n;
        uint32_t hi[8], lo[8];
#pragma unroll
        for (int j = 0; j < 8; j++) {
            float a = src[(size_t)(2*j)*HW], c = src[(size_t)(2*j+1)*HW];
            uint32_t hp = pack_bf16x2(a, c);
            hi[j] = hp;
            lo[j] = resid_pack(hp, a, c);
        }
        uint4* dh = (sel ? g_kh : g_qh) + ((size_t)b*HW + n)*2;
        uint4* dl = (sel ? g_kl : g_ql) + ((size_t)b*HW + n)*2;
        dh[0] = make_uint4(hi[0], hi[1], hi[2], hi[3]);
        dh[1] = make_uint4(hi[4], hi[5], hi[6], hi[7]);
        dl[0] = make_uint4(lo[0], lo[1], lo[2], lo[3]);
        dl[1] = make_uint4(lo[4], lo[5], lo[6], lo[7]);
    } else {
        int i = gid - 32768;
        if (i >= BB*CO*HW/4) return;
        float4 v = ((const float4*)g_v)[i];
        uint32_t h0 = pack_bf16x2(v.x, v.y);
        uint32_t h1 = pack_bf16x2(v.z, v.w);
        g_vh32[2*i]   = h0;
        g_vh32[2*i+1] = h1;
        g_vl32[2*i]   = resid_pack(h0, v.x, v.y);
        g_vl32[2*i+1] = resid_pack(h1, v.z, v.w);
    }
}

// ---------------------------------------------------------------------------
// MMA attention + fused z-projection. (unchanged from R9)
// ---------------------------------------------------------------------------
#define AQH 0
#define AQL 6144
#define AKH 12288
#define AKL 18432
#define AVH 24576
#define AVL 41984
#define AZH 59392
#define AZL 68608
#define ATTN2_SMEM 77824

__global__ __launch_bounds__(256) void attn_mma(
    const float* __restrict__ zb, float* __restrict__ out, int tstep)
{
    extern __shared__ char sm[];
    const uint32_t sbase = smem_u32(sm);
    const int tid = threadIdx.x, lane = tid & 31, warp = tid >> 5;
    const int b = blockIdx.y, tile = blockIdx.x;
    const int n0 = tile * 128;

    {
        int row = tid & 127, term = tid >> 7;
        const uint4* src = (term ? g_ql : g_qh) + ((size_t)b*HW + n0 + row)*2;
        char* dst = sm + (term ? AQL : AQH) + row*48;
        ((uint4*)dst)[0] = src[0];
        ((uint4*)dst)[1] = src[1];
    }
    for (int i = tid; i < 1024; i += 256) {
        int term = i >> 9, r = (i >> 3) & 63, q = i & 7;
        const uint4* s32 = (const uint4*)(term ? g_zwl32 : g_zwh32);
        *(uint4*)(sm + (term ? AZL : AZH) + r*144 + q*16) = s32[r*8 + q];
    }
    __syncthreads();

    uint32_t aq_hi[4], aq_lo[4];
    {
        uint32_t aaddr = sbase + AQH
            + (warp*16 + (lane & 7) + ((lane >> 3) & 1)*8)*48 + (lane >> 4)*16;
        ldsm_x4(aaddr, aq_hi);
        ldsm_x4(aaddr + (AQL - AQH), aq_lo);
    }
    const uint32_t kaddr = sbase + AKH + ((lane & 7) + (lane >> 4)*8)*48
                         + ((lane >> 3) & 1)*16;
    const uint32_t vaddr = sbase + AVH + ((lane & 7) + (lane >> 4)*8)*272
                         + ((lane >> 3) & 1)*16;
    const uint32_t zaddr = sbase + AZH + ((lane & 7) + (lane >> 4)*8)*144
                         + ((lane >> 3) & 1)*16;

    float pv[8][4];
#pragma unroll
    for (int i = 0; i < 8; i++)
#pragma unroll
        for (int j = 0; j < 4; j++) pv[i][j] = 0.f;
    float L0 = 0.f, L1 = 0.f;

    for (int mt = 0; mt < 8; mt++) {
        __syncthreads();
        {
            int row = tid & 127, term = tid >> 7;
            const uint4* src = (term ? g_kl : g_kh)
                             + ((size_t)b*HW + mt*128 + row)*2;
            char* dst = sm + (term ? AKL : AKH) + row*48;
            ((uint4*)dst)[0] = src[0];
            ((uint4*)dst)[1] = src[1];
        }
#pragma unroll 2
        for (int i = tid; i < 2048; i += 256) {
            int term = i >> 10, r = (i >> 4) & 63, q = i & 15;
            const uint4* src = (const uint4*)(term ? g_vl32 : g_vh32);
            uint4 v = src[((size_t)(b*CO) + r)*128 + mt*16 + q];
            *(uint4*)(sm + (term ? AVL : AVH) + r*272 + q*16) = v;
        }
        __syncthreads();

        float sacc[16][4];
#pragma unroll
        for (int i = 0; i < 16; i++)
#pragma unroll
            for (int j = 0; j < 4; j++) sacc[i][j] = 0.f;
#pragma unroll
        for (int mg = 0; mg < 8; mg++) {
            uint32_t bh[4], bl[4];
            ldsm_x4(kaddr + mg*(16*48), bh);
            ldsm_x4(kaddr + (AKL - AKH) + mg*(16*48), bl);
            mma_bf16(sacc[2*mg],   aq_hi, bh[0], bh[1]);
            mma_bf16(sacc[2*mg+1], aq_hi, bh[2], bh[3]);
            mma_bf16(sacc[2*mg],   aq_lo, bh[0], bh[1]);
            mma_bf16(sacc[2*mg+1], aq_lo, bh[2], bh[3]);
            mma_bf16(sacc[2*mg],   aq_hi, bl[0], bl[1]);
            mma_bf16(sacc[2*mg+1], aq_hi, bl[2], bl[3]);
        }

#pragma unroll
        for (int j = 0; j < 8; j++) {
            float e0 = fexp(sacc[2*j][0]),   e1 = fexp(sacc[2*j][1]);
            float e2 = fexp(sacc[2*j][2]),   e3 = fexp(sacc[2*j][3]);
            float e4 = fexp(sacc[2*j+1][0]), e5 = fexp(sacc[2*j+1][1]);
            float e6 = fexp(sacc[2*j+1][2]), e7 = fexp(sacc[2*j+1][3]);
            L0 += e0 + e1 + e4 + e5;
            L1 += e2 + e3 + e6 + e7;
            uint32_t ah[4], al[4];
            ah[0] = pack_bf16x2(e0, e1); al[0] = resid_pack(ah[0], e0, e1);
            ah[1] = pack_bf16x2(e2, e3); al[1] = resid_pack(ah[1], e2, e3);
            ah[2] = pack_bf16x2(e4, e5); al[2] = resid_pack(ah[2], e4, e5);
            ah[3] = pack_bf16x2(e6, e7); al[3] = resid_pack(ah[3], e6, e7);
#pragma unroll
            for (int cg = 0; cg < 4; cg++) {
                uint32_t vh[4], vl[4];
                ldsm_x4(vaddr + cg*(16*272) + j*32, vh);
                ldsm_x4(vaddr + (AVL - AVH) + cg*(16*272) + j*32, vl);
                mma_bf16(pv[2*cg],   ah, vh[0], vh[1]);
                mma_bf16(pv[2*cg+1], ah, vh[2], vh[3]);
                mma_bf16(pv[2*cg],   al, vh[0], vh[1]);
                mma_bf16(pv[2*cg+1], al, vh[2], vh[3]);
                mma_bf16(pv[2*cg],   ah, vl[0], vl[1]);
                mma_bf16(pv[2*cg+1], ah, vl[2], vl[3]);
            }
        }
    }

    L0 += __shfl_xor_sync(0xFFFFFFFFu, L0, 1);
    L0 += __shfl_xor_sync(0xFFFFFFFFu, L0, 2);
    L1 += __shfl_xor_sync(0xFFFFFFFFu, L1, 1);
    L1 += __shfl_xor_sync(0xFFFFFFFFu, L1, 2);
    float inv0 = 1.f / L0, inv1 = 1.f / L1;

    float zp[8][4];
#pragma unroll
    for (int i = 0; i < 8; i++)
#pragma unroll
        for (int j = 0; j < 4; j++) zp[i][j] = 0.f;
#pragma unroll
    for (int ck = 0; ck < 4; ck++) {
        uint32_t ah[4], al[4];
        ah[0] = pack_bf16x2(pv[2*ck][0], pv[2*ck][1]);
        al[0] = resid_pack(ah[0], pv[2*ck][0], pv[2*ck][1]);
        ah[1] = pack_bf16x2(pv[2*ck][2], pv[2*ck][3]);
        al[1] = resid_pack(ah[1], pv[2*ck][2], pv[2*ck][3]);
        ah[2] = pack_bf16x2(pv[2*ck+1][0], pv[2*ck+1][1]);
        al[2] = resid_pack(ah[2], pv[2*ck+1][0], pv[2*ck+1][1]);
        ah[3] = pack_bf16x2(pv[2*ck+1][2], pv[2*ck+1][3]);
        al[3] = resid_pack(ah[3], pv[2*ck+1][2], pv[2*ck+1][3]);
#pragma unroll
        for (int cog = 0; cog < 4; cog++) {
            uint32_t bh[4], bl[4];
            ldsm_x4(zaddr + cog*(16*144) + ck*32, bh);
            ldsm_x4(zaddr + (AZL - AZH) + cog*(16*144) + ck*32, bl);
            mma_bf16(zp[2*cog],   ah, bh[0], bh[1]);
            mma_bf16(zp[2*cog+1], ah, bh[2], bh[3]);
            mma_bf16(zp[2*cog],   al, bh[0], bh[1]);
            mma_bf16(zp[2*cog+1], al, bh[2], bh[3]);
            mma_bf16(zp[2*cog],   ah, bl[0], bl[1]);
            mma_bf16(zp[2*cog+1], ah, bl[2], bl[3]);
        }
    }

    {
        const int r0 = warp*16 + (lane >> 2);
        const int pix = n0 + r0;
        uint32_t* hh = (uint32_t*)g_hhi + ((size_t)b*HW + pix)*32;
        uint32_t* hl = (uint32_t*)g_hlo + ((size_t)b*HW + pix)*32;
#pragma unroll
        for (int cog = 0; cog < 4; cog++) {
#pragma unroll
            for (int tt = 0; tt < 2; tt++) {
                int co = cog*16 + tt*8 + 2*(lane & 3);
                float bz0 = __ldg(zb + co), bz1 = __ldg(zb + co + 1);
                float v0 = zp[2*cog+tt][0]*inv0 + bz0;
                float v1 = zp[2*cog+tt][1]*inv0 + bz1;
                float v2 = zp[2*cog+tt][2]*inv1 + bz0;
                float v3 = zp[2*cog+tt][3]*inv1 + bz1;
                size_t o0 = ((size_t)(b*CO + co)*TT + tstep)*HW;
                size_t o1 = ((size_t)(b*CO + co + 1)*TT + tstep)*HW;
                out[o0 + pix]     = v0;
                out[o1 + pix]     = v1;
                out[o0 + pix + 8] = v2;
                out[o1 + pix + 8] = v3;
                int ci = cog*8 + tt*4 + (lane & 3);
                uint32_t hp0 = pack_bf16x2(v0, v1);
                hh[ci] = hp0;
                hl[ci] = resid_pack(hp0, v0, v1);
                uint32_t hp1 = pack_bf16x2(v2, v3);
                hh[256 + ci] = hp1;
                hl[256 + ci] = resid_pack(hp1, v2, v3);
            }
        }
    }
}

// ---------------------------------------------------------------------------
extern "C" void kernel_launch(void* const* d_in, const int* in_sizes, int n_in,
                              void* d_out, int out_size)
{
    (void)in_sizes; (void)n_in; (void)out_size;
    const float* X      = (const float*)d_in[0];
    const float* conv_w = (const float*)d_in[1];
    const float* conv_b = (const float*)d_in[2];
    const float* W_ci   = (const float*)d_in[3];
    const float* W_cf   = (const float*)d_in[4];
    const float* W_co   = (const float*)d_in[5];
    const float* q_w    = (const float*)d_in[6];
    const float* q_b    = (const float*)d_in[7];
    const float* k_w    = (const float*)d_in[8];
    const float* k_b    = (const float*)d_in[9];
    const float* v_w    = (const float*)d_in[10];
    const float* v_b    = (const float*)d_in[11];
    const float* z_w    = (const float*)d_in[12];
    const float* z_b    = (const float*)d_in[13];
    float* out = (float*)d_out;

    static cudaStream_t s2 = nullptr;
    static cudaEvent_t evFork = nullptr;
    static cudaEvent_t evX[TT];
    if (!s2) {
        cudaStreamCreateWithFlags(&s2, cudaStreamNonBlocking);
        cudaEventCreateWithFlags(&evFork, cudaEventDisableTiming);
        for (int t = 0; t < TT; t++)
            cudaEventCreateWithFlags(&evX[t], cudaEventDisableTiming);
        cudaFuncSetAttribute(conv_x_kernel,
            cudaFuncAttributeMaxDynamicSharedMemorySize, CONV_SMEM);
        cudaFuncSetAttribute(conv_h_kernel,
            cudaFuncAttributeMaxDynamicSharedMemorySize, CONV_SMEM);
        cudaFuncSetAttribute(qkv_kernel,
            cudaFuncAttributeMaxDynamicSharedMemorySize, QKV_SMEM);
        cudaFuncSetAttribute(attn_mma,
            cudaFuncAttributeMaxDynamicSharedMemorySize, ATTN2_SMEM);
    }

    zero_state<<<(BB*HW*CO + 255)/256, 256>>>();
    prep_weights<<<(18*16384 + 255)/256, 256>>>(conv_w);
    prep_peep<<<(3*CO*HW + 255)/256, 256>>>(W_ci, W_cf, W_co);
    prep_zw<<<8, 256>>>(z_w);
    prep_x<<<dim3(8, TT, BB), 256>>>(X);

    // fork: X-half convs for all timesteps run on s2, overlapped with the
    // recurrent chain; conv_h(t) waits on evX[t].
    cudaEventRecord(evFork, 0);
    cudaStreamWaitEvent(s2, evFork, 0);
    for (int t = 0; t < TT; t++) {
        conv_x_kernel<<<dim3(8, BB, 2), 256, CONV_SMEM, s2>>>(t);
        cudaEventRecord(evX[t], s2);
    }

    for (int t = 0; t < TT; t++) {
        cudaStreamWaitEvent(0, evX[t], 0);
        conv_h_kernel<<<dim3(8, BB, 2), 256, CONV_SMEM>>>(t);
        gates_kernel<<<(BB*HW*CO + 255)/256, 256>>>(conv_b);
        qkv_kernel<<<dim3(8, BB), 256, QKV_SMEM>>>(
            q_w, q_b, k_w, k_b, v_w, v_b);
        pack_qkv<<<(32768 + BB*CO*HW/4 + 255)/256, 256>>>();
        attn_mma<<<dim3(8, BB), 256, ATTN2_SMEM>>>(z_b, out, t);
    }
}